// round 13
// baseline (speedup 1.0000x reference)
#include <cuda_runtime.h>
#include <cuda_bf16.h>
#include <cuda_fp16.h>
#include <cstdint>

// Problem constants: B=8, N=1024, C=1024, H=16, D=64
#define BB 8
#define NN 1024
#define CC 1024
#define HH 16
#define DD 64
#define SCALE 0.125f

// ---------------------------------------------------------------------------
// Scratch (all fp16)
// ---------------------------------------------------------------------------
__device__ __half g_q16h[BB*HH*NN*DD];  // [bh][n][d], q pre-scaled by 1/8, hi
__device__ __half g_q16l[BB*HH*NN*DD];  // q lo (residual)
__device__ __half g_k16[BB*HH*NN*DD];   // k single fp16
__device__ __half g_v16[BB*HH*NN*DD];   // v single fp16

__device__ __half g_xh[BB*NN*CC];
__device__ __half g_xl[BB*NN*CC];
__device__ __half g_wi[3*CC*CC];
__device__ __half g_wo[CC*CC];
__device__ __half g_oh[BB*NN*CC];   // attention out hi, [B*N, C]
__device__ __half g_ol[BB*NN*CC];   // attention out lo

// ---------------------------------------------------------------------------
// Helpers
// ---------------------------------------------------------------------------
__device__ __forceinline__ uint32_t smem_to_u32(const void* p) {
    uint32_t a;
    asm("{ .reg .u64 t; cvta.to.shared.u64 t, %1; cvt.u32.u64 %0, t; }"
        : "=r"(a) : "l"(p));
    return a;
}
__device__ __forceinline__ void ldsm_x4(uint32_t r[4], uint32_t addr) {
    asm volatile("ldmatrix.sync.aligned.m8n8.x4.shared.b16 {%0,%1,%2,%3}, [%4];"
        : "=r"(r[0]), "=r"(r[1]), "=r"(r[2]), "=r"(r[3]) : "r"(addr));
}
__device__ __forceinline__ void ldsm_x4_t(uint32_t r[4], uint32_t addr) {
    asm volatile("ldmatrix.sync.aligned.m8n8.x4.trans.shared.b16 {%0,%1,%2,%3}, [%4];"
        : "=r"(r[0]), "=r"(r[1]), "=r"(r[2]), "=r"(r[3]) : "r"(addr));
}
// fp16 HMMA
__device__ __forceinline__ void mma16816h(float c[4], const uint32_t a[4],
                                          const uint32_t b[2]) {
    asm volatile(
        "mma.sync.aligned.m16n8k16.row.col.f32.f16.f16.f32 "
        "{%0,%1,%2,%3}, {%4,%5,%6,%7}, {%8,%9}, {%0,%1,%2,%3};"
        : "+f"(c[0]), "+f"(c[1]), "+f"(c[2]), "+f"(c[3])
        : "r"(a[0]), "r"(a[1]), "r"(a[2]), "r"(a[3]), "r"(b[0]), "r"(b[1]));
}
#define CP_ASYNC16(sa, ga) \
    asm volatile("cp.async.cg.shared.global [%0], [%1], 16;" \
                 :: "r"(sa), "l"(ga) : "memory")
#define CP_COMMIT() asm volatile("cp.async.commit_group;" ::: "memory")
#define CP_WAIT1()  asm volatile("cp.async.wait_group 1;" ::: "memory")
#define CP_WAIT0()  asm volatile("cp.async.wait_group 0;" ::: "memory")

__device__ __forceinline__ uint32_t swz(int row, int cx) {
    return (uint32_t)(row * 128) + ((uint32_t)(cx ^ (row & 7)) << 4);
}

// ---------------------------------------------------------------------------
// Prep kernels
// ---------------------------------------------------------------------------
__global__ void __launch_bounds__(256) split_fp16_kernel(
        const float* __restrict__ src, __half* __restrict__ hi,
        __half* __restrict__ lo, int n) {
    int i = blockIdx.x * 256 + threadIdx.x;
    if (i < n) {
        float x = src[i];
        __half h = __float2half(x);
        hi[i] = h;
        lo[i] = __float2half(x - __half2float(h));
    }
}
__global__ void __launch_bounds__(256) cvt_fp16_kernel(
        const float* __restrict__ src, __half* __restrict__ dst, int n) {
    int i = blockIdx.x * 256 + threadIdx.x;
    if (i < n) dst[i] = __float2half(src[i]);
}

// ---------------------------------------------------------------------------
// fp16 asymmetric-split GEMM: D = (Ahi+Alo) @ B^T + bias
// Tile 128x128, K-chunk 32. A smem row (128B) = [32 f16 hi | 32 f16 lo],
// B tile uses cx0-3 only. 4 HMMA per k32 per warp-tile pair.
// 3-stage cp.async (96KB) -> 2 CTAs/SM.
// mode 0: scatter qkv (q dual fp16 scaled; k,v single fp16); mode 1: fp32 out.
// ---------------------------------------------------------------------------
#define STG_STRIDE 32768
#define T_B 16384
#define GEMM_SMEM (3 * STG_STRIDE)

__global__ void __launch_bounds__(256, 2) gemm_fp16_kernel(
        const __half* __restrict__ Ahi, const __half* __restrict__ Alo,
        const __half* __restrict__ Bw,
        const float* __restrict__ bias, float* __restrict__ outp, int mode) {
    extern __shared__ char smem[];
    const uint32_t sbase = smem_to_u32(smem);
    const int tid = threadIdx.x;
    const int wid = tid >> 5, lane = tid & 31;
    const int wm = wid >> 2, wn = wid & 3;
    const int row0 = blockIdx.y * 128, col0 = blockIdx.x * 128;
    const int mat = lane >> 3, rin = lane & 7;

    float cacc[4][4][4];
#pragma unroll
    for (int mi = 0; mi < 4; mi++)
#pragma unroll
        for (int nj = 0; nj < 4; nj++)
#pragma unroll
            for (int e = 0; e < 4; e++) cacc[mi][nj][e] = 0.f;

    auto issue = [&](int stage, int c) {
        const int k0 = c * 32;
        const uint32_t sst = sbase + stage * STG_STRIDE;
#pragma unroll
        for (int p = 0; p < 4; p++) {
            int id = tid + p * 256;
            int row = id >> 3, cx = id & 7;
            uint32_t dst = swz(row, cx);
            int kg = k0 + (cx & 3) * 8;
            size_t sa = (size_t)(row0 + row) * 1024 + kg;
            CP_ASYNC16(sst + dst, (cx < 4) ? (Ahi + sa) : (Alo + sa));
        }
#pragma unroll
        for (int p = 0; p < 2; p++) {
            int id = tid + p * 256;
            int row = id >> 2, cx = id & 3;
            uint32_t dst = swz(row, cx);
            size_t sb = (size_t)(col0 + row) * 1024 + k0 + cx * 8;
            CP_ASYNC16(sst + T_B + dst, Bw + sb);
        }
        CP_COMMIT();
    };

    auto compute = [&](int stage) {
        const uint32_t sA = sbase + stage * STG_STRIDE;
#pragma unroll
        for (int s = 0; s < 2; s++) {
            uint32_t ah[4][4], al[4][4], bf[4][2];
            const int cxh = s * 2 + (mat >> 1);
            const int cxl = cxh + 4;
#pragma unroll
            for (int mi = 0; mi < 4; mi++) {
                int row = wm * 64 + mi * 16 + rin + (mat & 1) * 8;
                ldsm_x4(ah[mi], sA + swz(row, cxh));
                ldsm_x4(al[mi], sA + swz(row, cxl));
            }
#pragma unroll
            for (int nf = 0; nf < 2; nf++) {
                int row = wn * 32 + nf * 16 + rin + (mat & 1) * 8;
                uint32_t t[4];
                ldsm_x4(t, sA + T_B + swz(row, cxh));
                bf[nf*2][0] = t[0]; bf[nf*2][1] = t[2];
                bf[nf*2+1][0] = t[1]; bf[nf*2+1][1] = t[3];
            }
#pragma unroll
            for (int mi = 0; mi < 4; mi++)
#pragma unroll
                for (int nj = 0; nj < 4; nj++)
                    mma16816h(cacc[mi][nj], ah[mi], bf[nj]);
#pragma unroll
            for (int mi = 0; mi < 4; mi++)
#pragma unroll
                for (int nj = 0; nj < 4; nj++)
                    mma16816h(cacc[mi][nj], al[mi], bf[nj]);
        }
    };

    auto step = [&](int c, int stage, int nxt) {
        if (c < 31) CP_WAIT1(); else CP_WAIT0();
        __syncthreads();
        if (c + 2 < 32) issue(nxt, c + 2);
        compute(stage);
    };

    issue(0, 0); issue(1, 1);
#pragma unroll 1
    for (int cb = 0; cb < 30; cb += 3) {
        step(cb + 0, 0, 2);
        step(cb + 1, 1, 0);
        step(cb + 2, 2, 1);
    }
    step(30, 0, 2);
    step(31, 1, 0);

    const int g = lane >> 2, c4 = lane & 3;
#pragma unroll
    for (int mi = 0; mi < 4; mi++)
#pragma unroll
        for (int h2 = 0; h2 < 2; h2++) {
            int row = row0 + wm * 64 + mi * 16 + g + h2 * 8;
            int b = row >> 10, n_ = row & 1023;
#pragma unroll
            for (int nj = 0; nj < 4; nj++) {
                int col = col0 + wn * 32 + nj * 8 + c4 * 2;
                float v0 = cacc[mi][nj][h2 * 2 + 0] + bias[col];
                float v1 = cacc[mi][nj][h2 * 2 + 1] + bias[col + 1];
                if (mode == 0) {
                    int sec = col >> 10;
                    int ci = col & 1023;
                    int hh = ci >> 6, d = ci & 63;
                    size_t idx = ((size_t)(((b * 16 + hh) << 10) | n_)) * 64 + d;
                    if (sec == 0) {
                        v0 *= SCALE; v1 *= SCALE;
                        __half2 hi2 = __floats2half2_rn(v0, v1);
                        __half2 lo2 = __floats2half2_rn(
                            v0 - __half2float(__low2half(hi2)),
                            v1 - __half2float(__high2half(hi2)));
                        *(uint32_t*)&g_q16h[idx] = *(uint32_t*)&hi2;
                        *(uint32_t*)&g_q16l[idx] = *(uint32_t*)&lo2;
                    } else {
                        __half2 hi2 = __floats2half2_rn(v0, v1);
                        __half* dst = (sec == 1) ? g_k16 : g_v16;
                        *(uint32_t*)&dst[idx] = *(uint32_t*)&hi2;
                    }
                } else {
                    float2 vv = make_float2(v0, v1);
                    *(float2*)&outp[(size_t)row * 1024 + col] = vv;
                }
            }
        }
}

// ---------------------------------------------------------------------------
// fp16 flash attention. One CTA per (bh, 128-query tile); 8 warps.
// S = (Qh+Ql) @ K1^T   (4 HMMA per (s,t))
// O += (Ph+Pl) @ V1    (4 HMMA per (s,t))
// Smem: Qh 16K | Ql 16K | 2 stages x (K 8K + V 8K) = 64KB total.
// ---------------------------------------------------------------------------
#define AT_SQH 0
#define AT_SQL 16384
#define AT_ST0 32768
#define AT_K 0
#define AT_V 8192
#define AT_STRIDE 16384
#define ATTN_SMEM 65536

__global__ void __launch_bounds__(256, 2) attn_mma_kernel() {
    extern __shared__ char smem[];
    const uint32_t sbase = smem_to_u32(smem);
    const int tid = threadIdx.x;
    const int wid = tid >> 5, lane = tid & 31;
    const int bh = blockIdx.y, q0 = blockIdx.x * 128;
    const int b = bh >> 4, h = bh & 15;
    const int mat = lane >> 3, rin = lane & 7;
    const int g = lane >> 2, c4 = lane & 3;

    const __half* __restrict__ qhp = g_q16h + (size_t)bh * NN * DD;
    const __half* __restrict__ qlp = g_q16l + (size_t)bh * NN * DD;
    const __half* __restrict__ kp  = g_k16  + (size_t)bh * NN * DD;
    const __half* __restrict__ vp  = g_v16  + (size_t)bh * NN * DD;

    // Q tile load (hi+lo): 1024 chunks each
#pragma unroll
    for (int p = 0; p < 4; p++) {
        int chunk = tid + p * 256;
        int row = chunk >> 3, cx = chunk & 7;
        uint32_t dst = swz(row, cx);
        size_t src = (size_t)(q0 + row) * 64 + cx * 8;
        CP_ASYNC16(sbase + AT_SQH + dst, qhp + src);
        CP_ASYNC16(sbase + AT_SQL + dst, qlp + src);
    }
    CP_COMMIT();

    auto issue_kv = [&](int st, int kt) {
        const uint32_t sb = sbase + AT_ST0 + st * AT_STRIDE;
        const size_t base = (size_t)(kt * 64) * 64;
#pragma unroll
        for (int p = 0; p < 2; p++) {
            int chunk = tid + p * 256;
            int row = chunk >> 3, cx = chunk & 7;
            uint32_t dst = swz(row, cx);
            size_t src = base + (size_t)row * 64 + cx * 8;
            CP_ASYNC16(sb + AT_K + dst, kp + src);
            CP_ASYNC16(sb + AT_V + dst, vp + src);
        }
        CP_COMMIT();
    };
    issue_kv(0, 0);
    issue_kv(1, 1);

    float m0 = -1e30f, m1 = -1e30f, l0 = 0.f, l1 = 0.f;
    float oacc[8][4];
#pragma unroll
    for (int i = 0; i < 8; i++)
#pragma unroll
        for (int e = 0; e < 4; e++) oacc[i][e] = 0.f;

    auto astep = [&](int kt, int st) {
        if (kt < 15) CP_WAIT1(); else CP_WAIT0();
        __syncthreads();
        const uint32_t skv = sbase + AT_ST0 + st * AT_STRIDE;

        // ---- S = (Qh+Ql) @ K^T ----
        float sacc[8][4];
#pragma unroll
        for (int i = 0; i < 8; i++)
#pragma unroll
            for (int e = 0; e < 4; e++) sacc[i][e] = 0.f;

#pragma unroll
        for (int s = 0; s < 4; s++) {
            const int cx = s * 2 + (mat >> 1);
            uint32_t qh[4], ql[4];
            {
                int row = wid * 16 + (mat & 1) * 8 + rin;
                uint32_t off = swz(row, cx);
                ldsm_x4(qh, sbase + AT_SQH + off);
                ldsm_x4(ql, sbase + AT_SQL + off);
            }
#pragma unroll
            for (int t = 0; t < 4; t++) {
                int krow = t * 16 + (mat & 1) * 8 + rin;
                uint32_t off = swz(krow, cx);
                uint32_t th[4];
                ldsm_x4(th, skv + AT_K + off);
                uint32_t bh0[2] = {th[0], th[2]}, bh1[2] = {th[1], th[3]};
                mma16816h(sacc[2*t],   qh, bh0);
                mma16816h(sacc[2*t+1], qh, bh1);
                mma16816h(sacc[2*t],   ql, bh0);
                mma16816h(sacc[2*t+1], ql, bh1);
            }
        }

        // ---- online softmax (warp-local) ----
        float mx0 = -1e30f, mx1 = -1e30f;
#pragma unroll
        for (int i = 0; i < 8; i++) {
            mx0 = fmaxf(mx0, fmaxf(sacc[i][0], sacc[i][1]));
            mx1 = fmaxf(mx1, fmaxf(sacc[i][2], sacc[i][3]));
        }
        mx0 = fmaxf(mx0, __shfl_xor_sync(0xffffffffu, mx0, 1));
        mx0 = fmaxf(mx0, __shfl_xor_sync(0xffffffffu, mx0, 2));
        mx1 = fmaxf(mx1, __shfl_xor_sync(0xffffffffu, mx1, 1));
        mx1 = fmaxf(mx1, __shfl_xor_sync(0xffffffffu, mx1, 2));
        float mn0 = fmaxf(m0, mx0), mn1 = fmaxf(m1, mx1);
        float al0 = __expf(m0 - mn0), al1 = __expf(m1 - mn1);
        m0 = mn0; m1 = mn1;
        float rs0 = 0.f, rs1 = 0.f;
#pragma unroll
        for (int i = 0; i < 8; i++) {
            sacc[i][0] = __expf(sacc[i][0] - mn0);
            sacc[i][1] = __expf(sacc[i][1] - mn0);
            sacc[i][2] = __expf(sacc[i][2] - mn1);
            sacc[i][3] = __expf(sacc[i][3] - mn1);
            rs0 += sacc[i][0] + sacc[i][1];
            rs1 += sacc[i][2] + sacc[i][3];
        }
        rs0 += __shfl_xor_sync(0xffffffffu, rs0, 1);
        rs0 += __shfl_xor_sync(0xffffffffu, rs0, 2);
        rs1 += __shfl_xor_sync(0xffffffffu, rs1, 1);
        rs1 += __shfl_xor_sync(0xffffffffu, rs1, 2);
        l0 = l0 * al0 + rs0;
        l1 = l1 * al1 + rs1;
#pragma unroll
        for (int i = 0; i < 8; i++) {
            oacc[i][0] *= al0; oacc[i][1] *= al0;
            oacc[i][2] *= al1; oacc[i][3] *= al1;
        }

        // ---- O += (Ph+Pl) @ V ----
#pragma unroll
        for (int s = 0; s < 4; s++) {
            uint32_t ph[4], pl[4];
            {
                float e0 = sacc[2*s][0], e1 = sacc[2*s][1];
                float e2 = sacc[2*s][2], e3 = sacc[2*s][3];
                float f0 = sacc[2*s+1][0], f1 = sacc[2*s+1][1];
                float f2 = sacc[2*s+1][2], f3 = sacc[2*s+1][3];
                __half2 t0 = __floats2half2_rn(e0, e1);
                __half2 t1 = __floats2half2_rn(e2, e3);
                __half2 t2 = __floats2half2_rn(f0, f1);
                __half2 t3 = __floats2half2_rn(f2, f3);
                ph[0] = *(uint32_t*)&t0; ph[1] = *(uint32_t*)&t1;
                ph[2] = *(uint32_t*)&t2; ph[3] = *(uint32_t*)&t3;
                __half2 u0 = __floats2half2_rn(
                    e0 - __half2float(__low2half(t0)),
                    e1 - __half2float(__high2half(t0)));
                __half2 u1 = __floats2half2_rn(
                    e2 - __half2float(__low2half(t1)),
                    e3 - __half2float(__high2half(t1)));
                __half2 u2 = __floats2half2_rn(
                    f0 - __half2float(__low2half(t2)),
                    f1 - __half2float(__high2half(t2)));
                __half2 u3 = __floats2half2_rn(
                    f2 - __half2float(__low2half(t3)),
                    f3 - __half2float(__high2half(t3)));
                pl[0] = *(uint32_t*)&u0; pl[1] = *(uint32_t*)&u1;
                pl[2] = *(uint32_t*)&u2; pl[3] = *(uint32_t*)&u3;
            }
#pragma unroll
            for (int t = 0; t < 4; t++) {
                int vrow = s * 16 + (mat >> 1) * 8 + rin;
                int cxv = t * 2 + (mat & 1);
                uint32_t off = swz(vrow, cxv);
                uint32_t th[4];
                ldsm_x4_t(th, skv + AT_V + off);
                uint32_t vh0[2] = {th[0], th[2]}, vh1[2] = {th[1], th[3]};
                mma16816h(oacc[2*t],   ph, vh0);
                mma16816h(oacc[2*t+1], ph, vh1);
                mma16816h(oacc[2*t],   pl, vh0);
                mma16816h(oacc[2*t+1], pl, vh1);
            }
        }
        __syncthreads();
        if (kt + 2 < 16) issue_kv(st, kt + 2);
    };

#pragma unroll 1
    for (int kt = 0; kt < 16; kt += 2) {
        astep(kt, 0);
        astep(kt + 1, 1);
    }

    // epilogue: normalize, split fp16 hi/lo, write [B*N, C]
    float inv0 = 1.f / l0, inv1 = 1.f / l1;
    int r0 = q0 + wid * 16 + g;
    int r1 = r0 + 8;
#pragma unroll
    for (int nj = 0; nj < 8; nj++) {
        int col = h * 64 + nj * 8 + c4 * 2;
        {
            float v0 = oacc[nj][0] * inv0, v1 = oacc[nj][1] * inv0;
            __half2 hi2 = __floats2half2_rn(v0, v1);
            __half2 lo2 = __floats2half2_rn(
                v0 - __half2float(__low2half(hi2)),
                v1 - __half2float(__high2half(hi2)));
            size_t idx = (size_t)(b * 1024 + r0) * 1024 + col;
            *(uint32_t*)&g_oh[idx] = *(uint32_t*)&hi2;
            *(uint32_t*)&g_ol[idx] = *(uint32_t*)&lo2;
        }
        {
            float v0 = oacc[nj][2] * inv1, v1 = oacc[nj][3] * inv1;
            __half2 hi2 = __floats2half2_rn(v0, v1);
            __half2 lo2 = __floats2half2_rn(
                v0 - __half2float(__low2half(hi2)),
                v1 - __half2float(__high2half(hi2)));
            size_t idx = (size_t)(b * 1024 + r1) * 1024 + col;
            *(uint32_t*)&g_oh[idx] = *(uint32_t*)&hi2;
            *(uint32_t*)&g_ol[idx] = *(uint32_t*)&lo2;
        }
    }
}

// ---------------------------------------------------------------------------
extern "C" void kernel_launch(void* const* d_in, const int* in_sizes, int n_in,
                              void* d_out, int out_size) {
    const float* x     = (const float*)d_in[0];
    const float* w_in  = (const float*)d_in[1];
    const float* b_in  = (const float*)d_in[2];
    const float* w_out = (const float*)d_in[3];
    const float* b_out = (const float*)d_in[4];
    float* out = (float*)d_out;

    static bool attr_set = false;
    if (!attr_set) {
        cudaFuncSetAttribute(gemm_fp16_kernel,
                             cudaFuncAttributeMaxDynamicSharedMemorySize, GEMM_SMEM);
        cudaFuncSetAttribute(attn_mma_kernel,
                             cudaFuncAttributeMaxDynamicSharedMemorySize, ATTN_SMEM);
        attr_set = true;
    }

    __half *xh, *xl, *wi, *wo, *oh, *ol;
    cudaGetSymbolAddress((void**)&xh, g_xh);
    cudaGetSymbolAddress((void**)&xl, g_xl);
    cudaGetSymbolAddress((void**)&wi, g_wi);
    cudaGetSymbolAddress((void**)&wo, g_wo);
    cudaGetSymbolAddress((void**)&oh, g_oh);
    cudaGetSymbolAddress((void**)&ol, g_ol);

    const int nx = BB*NN*CC, nwi = 3*CC*CC, nwo = CC*CC;

    // 1) prep: fp16 dual-split of x; fp16 casts of weights
    split_fp16_kernel<<<(nx + 255) / 256, 256>>>(x, xh, xl, nx);
    cvt_fp16_kernel<<<(nwi + 255) / 256, 256>>>(w_in, wi, nwi);
    cvt_fp16_kernel<<<(nwo + 255) / 256, 256>>>(w_out, wo, nwo);

    // 2) QKV projection (fp16 asymmetric split; writes fp16 q dual + k/v single)
    gemm_fp16_kernel<<<dim3(24, 64), 256, GEMM_SMEM>>>(
        xh, xl, wi, b_in, nullptr, 0);

    // 3) fp16 flash attention
    attn_mma_kernel<<<dim3(8, 128), 256, ATTN_SMEM>>>();

    // 4) out projection (fp16 asymmetric split)
    gemm_fp16_kernel<<<dim3(8, 64), 256, GEMM_SMEM>>>(
        oh, ol, wo, b_out, out, 1);
}

// round 15
// speedup vs baseline: 1.4963x; 1.4963x over previous
#include <cuda_runtime.h>
#include <cuda_bf16.h>
#include <cuda_fp16.h>
#include <cstdint>

// Problem constants: B=8, N=1024, C=1024, H=16, D=64
#define BB 8
#define NN 1024
#define CC 1024
#define HH 16
#define DD 64
#define SCALE 0.125f

// ---------------------------------------------------------------------------
// Scratch (all fp16). q/k/v stored as hi/lo pairs (epilogue shape == R11);
// attention reads q hi+lo, k hi only, v hi only.
// ---------------------------------------------------------------------------
__device__ __half g_qh16[BB*HH*NN*DD];  // [bh][n][d], q pre-scaled by 1/8
__device__ __half g_ql16[BB*HH*NN*DD];
__device__ __half g_kh16[BB*HH*NN*DD];
__device__ __half g_kl16[BB*HH*NN*DD];  // written, not read
__device__ __half g_vh16[BB*HH*NN*DD];
__device__ __half g_vl16[BB*HH*NN*DD];  // written, not read

__device__ __half g_xh[BB*NN*CC];
__device__ __half g_xl[BB*NN*CC];
__device__ __half g_wi[3*CC*CC];
__device__ __half g_wo[CC*CC];
__device__ __half g_oh[BB*NN*CC];   // attention out hi, [B*N, C]
__device__ __half g_ol[BB*NN*CC];   // attention out lo

// ---------------------------------------------------------------------------
// Helpers
// ---------------------------------------------------------------------------
__device__ __forceinline__ uint32_t smem_to_u32(const void* p) {
    uint32_t a;
    asm("{ .reg .u64 t; cvta.to.shared.u64 t, %1; cvt.u32.u64 %0, t; }"
        : "=r"(a) : "l"(p));
    return a;
}
__device__ __forceinline__ void ldsm_x4(uint32_t r[4], uint32_t addr) {
    asm volatile("ldmatrix.sync.aligned.m8n8.x4.shared.b16 {%0,%1,%2,%3}, [%4];"
        : "=r"(r[0]), "=r"(r[1]), "=r"(r[2]), "=r"(r[3]) : "r"(addr));
}
__device__ __forceinline__ void ldsm_x4_t(uint32_t r[4], uint32_t addr) {
    asm volatile("ldmatrix.sync.aligned.m8n8.x4.trans.shared.b16 {%0,%1,%2,%3}, [%4];"
        : "=r"(r[0]), "=r"(r[1]), "=r"(r[2]), "=r"(r[3]) : "r"(addr));
}
// fp16 HMMA
__device__ __forceinline__ void mma16816h(float c[4], const uint32_t a[4],
                                          const uint32_t b[2]) {
    asm volatile(
        "mma.sync.aligned.m16n8k16.row.col.f32.f16.f16.f32 "
        "{%0,%1,%2,%3}, {%4,%5,%6,%7}, {%8,%9}, {%0,%1,%2,%3};"
        : "+f"(c[0]), "+f"(c[1]), "+f"(c[2]), "+f"(c[3])
        : "r"(a[0]), "r"(a[1]), "r"(a[2]), "r"(a[3]), "r"(b[0]), "r"(b[1]));
}
#define CP_ASYNC16(sa, ga) \
    asm volatile("cp.async.cg.shared.global [%0], [%1], 16;" \
                 :: "r"(sa), "l"(ga) : "memory")
#define CP_COMMIT() asm volatile("cp.async.commit_group;" ::: "memory")
#define CP_WAIT1()  asm volatile("cp.async.wait_group 1;" ::: "memory")
#define CP_WAIT0()  asm volatile("cp.async.wait_group 0;" ::: "memory")

__device__ __forceinline__ uint32_t swz(int row, int cx) {
    return (uint32_t)(row * 128) + ((uint32_t)(cx ^ (row & 7)) << 4);
}

// ---------------------------------------------------------------------------
// Prep kernels
// ---------------------------------------------------------------------------
__global__ void __launch_bounds__(256) split_fp16_kernel(
        const float* __restrict__ src, __half* __restrict__ hi,
        __half* __restrict__ lo, int n) {
    int i = blockIdx.x * 256 + threadIdx.x;
    if (i < n) {
        float x = src[i];
        __half h = __float2half(x);
        hi[i] = h;
        lo[i] = __float2half(x - __half2float(h));
    }
}
__global__ void __launch_bounds__(256) cvt_fp16_kernel(
        const float* __restrict__ src, __half* __restrict__ dst, int n) {
    int i = blockIdx.x * 256 + threadIdx.x;
    if (i < n) dst[i] = __float2half(src[i]);
}

// ---------------------------------------------------------------------------
// fp16 asymmetric-split GEMM: D = (Ahi+Alo) @ B^T + bias
// Tile 128x128, K-chunk 32. A smem row (128B) = [32 f16 hi | 32 f16 lo],
// B tile uses cx0-3 only. 4 HMMA per k32 per warp-tile pair.
// 3-stage cp.async (96KB) -> 2 CTAs/SM.
// mode 0: scatter qkv as fp16 hi/lo pairs (q scaled) — R11 epilogue shape.
// mode 1: fp32 out.
// ---------------------------------------------------------------------------
#define STG_STRIDE 32768
#define T_B 16384
#define GEMM_SMEM (3 * STG_STRIDE)

__global__ void __launch_bounds__(256, 2) gemm_fp16_kernel(
        const __half* __restrict__ Ahi, const __half* __restrict__ Alo,
        const __half* __restrict__ Bw,
        const float* __restrict__ bias, float* __restrict__ outp, int mode) {
    extern __shared__ char smem[];
    const uint32_t sbase = smem_to_u32(smem);
    const int tid = threadIdx.x;
    const int wid = tid >> 5, lane = tid & 31;
    const int wm = wid >> 2, wn = wid & 3;
    const int row0 = blockIdx.y * 128, col0 = blockIdx.x * 128;
    const int mat = lane >> 3, rin = lane & 7;

    float cacc[4][4][4];
#pragma unroll
    for (int mi = 0; mi < 4; mi++)
#pragma unroll
        for (int nj = 0; nj < 4; nj++)
#pragma unroll
            for (int e = 0; e < 4; e++) cacc[mi][nj][e] = 0.f;

    auto issue = [&](int stage, int c) {
        const int k0 = c * 32;
        const uint32_t sst = sbase + stage * STG_STRIDE;
#pragma unroll
        for (int p = 0; p < 4; p++) {
            int id = tid + p * 256;
            int row = id >> 3, cx = id & 7;
            uint32_t dst = swz(row, cx);
            int kg = k0 + (cx & 3) * 8;
            size_t sa = (size_t)(row0 + row) * 1024 + kg;
            CP_ASYNC16(sst + dst, (cx < 4) ? (Ahi + sa) : (Alo + sa));
        }
#pragma unroll
        for (int p = 0; p < 2; p++) {
            int id = tid + p * 256;
            int row = id >> 2, cx = id & 3;
            uint32_t dst = swz(row, cx);
            size_t sb = (size_t)(col0 + row) * 1024 + k0 + cx * 8;
            CP_ASYNC16(sst + T_B + dst, Bw + sb);
        }
        CP_COMMIT();
    };

    auto compute = [&](int stage) {
        const uint32_t sA = sbase + stage * STG_STRIDE;
#pragma unroll
        for (int s = 0; s < 2; s++) {
            uint32_t ah[4][4], al[4][4], bf[4][2];
            const int cxh = s * 2 + (mat >> 1);
            const int cxl = cxh + 4;
#pragma unroll
            for (int mi = 0; mi < 4; mi++) {
                int row = wm * 64 + mi * 16 + rin + (mat & 1) * 8;
                ldsm_x4(ah[mi], sA + swz(row, cxh));
                ldsm_x4(al[mi], sA + swz(row, cxl));
            }
#pragma unroll
            for (int nf = 0; nf < 2; nf++) {
                int row = wn * 32 + nf * 16 + rin + (mat & 1) * 8;
                uint32_t t[4];
                ldsm_x4(t, sA + T_B + swz(row, cxh));
                bf[nf*2][0] = t[0]; bf[nf*2][1] = t[2];
                bf[nf*2+1][0] = t[1]; bf[nf*2+1][1] = t[3];
            }
#pragma unroll
            for (int mi = 0; mi < 4; mi++)
#pragma unroll
                for (int nj = 0; nj < 4; nj++)
                    mma16816h(cacc[mi][nj], ah[mi], bf[nj]);
#pragma unroll
            for (int mi = 0; mi < 4; mi++)
#pragma unroll
                for (int nj = 0; nj < 4; nj++)
                    mma16816h(cacc[mi][nj], al[mi], bf[nj]);
        }
    };

    auto step = [&](int c, int stage, int nxt) {
        if (c < 31) CP_WAIT1(); else CP_WAIT0();
        __syncthreads();
        if (c + 2 < 32) issue(nxt, c + 2);
        compute(stage);
    };

    issue(0, 0); issue(1, 1);
#pragma unroll 1
    for (int cb = 0; cb < 30; cb += 3) {
        step(cb + 0, 0, 2);
        step(cb + 1, 1, 0);
        step(cb + 2, 2, 1);
    }
    step(30, 0, 2);
    step(31, 1, 0);

    const int g = lane >> 2, c4 = lane & 3;
#pragma unroll
    for (int mi = 0; mi < 4; mi++)
#pragma unroll
        for (int h2 = 0; h2 < 2; h2++) {
            int row = row0 + wm * 64 + mi * 16 + g + h2 * 8;
            int b = row >> 10, n_ = row & 1023;
#pragma unroll
            for (int nj = 0; nj < 4; nj++) {
                int col = col0 + wn * 32 + nj * 8 + c4 * 2;
                float v0 = cacc[mi][nj][h2 * 2 + 0] + bias[col];
                float v1 = cacc[mi][nj][h2 * 2 + 1] + bias[col + 1];
                if (mode == 0) {
                    int sec = col >> 10;
                    int ci = col & 1023;
                    int hh = ci >> 6, d = ci & 63;
                    if (sec == 0) { v0 *= SCALE; v1 *= SCALE; }
                    __half2 hi2 = __floats2half2_rn(v0, v1);
                    __half2 lo2 = __floats2half2_rn(
                        v0 - __half2float(__low2half(hi2)),
                        v1 - __half2float(__high2half(hi2)));
                    size_t idx = ((size_t)(((b * 16 + hh) << 10) | n_)) * 64 + d;
                    __half *dh = (sec == 0) ? g_qh16 : (sec == 1) ? g_kh16 : g_vh16;
                    __half *dl = (sec == 0) ? g_ql16 : (sec == 1) ? g_kl16 : g_vl16;
                    *(uint32_t*)&dh[idx] = *(uint32_t*)&hi2;
                    *(uint32_t*)&dl[idx] = *(uint32_t*)&lo2;
                } else {
                    float2 vv = make_float2(v0, v1);
                    *(float2*)&outp[(size_t)row * 1024 + col] = vv;
                }
            }
        }
}

// ---------------------------------------------------------------------------
// fp16 flash attention. One CTA per (bh, 128-query tile); 8 warps.
// S = (Qh+Ql) @ K1^T   (4 HMMA per (s,t))
// O += (Ph+Pl) @ V1    (4 HMMA per (s,t))
// Smem: Qh 16K | Ql 16K | 2 stages x (K 8K + V 8K) = 64KB total.
// ---------------------------------------------------------------------------
#define AT_SQH 0
#define AT_SQL 16384
#define AT_ST0 32768
#define AT_K 0
#define AT_V 8192
#define AT_STRIDE 16384
#define ATTN_SMEM 65536

__global__ void __launch_bounds__(256, 2) attn_mma_kernel() {
    extern __shared__ char smem[];
    const uint32_t sbase = smem_to_u32(smem);
    const int tid = threadIdx.x;
    const int wid = tid >> 5, lane = tid & 31;
    const int bh = blockIdx.y, q0 = blockIdx.x * 128;
    const int b = bh >> 4, h = bh & 15;
    const int mat = lane >> 3, rin = lane & 7;
    const int g = lane >> 2, c4 = lane & 3;

    const __half* __restrict__ qhp = g_qh16 + (size_t)bh * NN * DD;
    const __half* __restrict__ qlp = g_ql16 + (size_t)bh * NN * DD;
    const __half* __restrict__ kp  = g_kh16 + (size_t)bh * NN * DD;
    const __half* __restrict__ vp  = g_vh16 + (size_t)bh * NN * DD;

    // Q tile load (hi+lo)
#pragma unroll
    for (int p = 0; p < 4; p++) {
        int chunk = tid + p * 256;
        int row = chunk >> 3, cx = chunk & 7;
        uint32_t dst = swz(row, cx);
        size_t src = (size_t)(q0 + row) * 64 + cx * 8;
        CP_ASYNC16(sbase + AT_SQH + dst, qhp + src);
        CP_ASYNC16(sbase + AT_SQL + dst, qlp + src);
    }
    CP_COMMIT();

    auto issue_kv = [&](int st, int kt) {
        const uint32_t sb = sbase + AT_ST0 + st * AT_STRIDE;
        const size_t base = (size_t)(kt * 64) * 64;
#pragma unroll
        for (int p = 0; p < 2; p++) {
            int chunk = tid + p * 256;
            int row = chunk >> 3, cx = chunk & 7;
            uint32_t dst = swz(row, cx);
            size_t src = base + (size_t)row * 64 + cx * 8;
            CP_ASYNC16(sb + AT_K + dst, kp + src);
            CP_ASYNC16(sb + AT_V + dst, vp + src);
        }
        CP_COMMIT();
    };
    issue_kv(0, 0);
    issue_kv(1, 1);

    float m0 = -1e30f, m1 = -1e30f, l0 = 0.f, l1 = 0.f;
    float oacc[8][4];
#pragma unroll
    for (int i = 0; i < 8; i++)
#pragma unroll
        for (int e = 0; e < 4; e++) oacc[i][e] = 0.f;

    auto astep = [&](int kt, int st) {
        if (kt < 15) CP_WAIT1(); else CP_WAIT0();
        __syncthreads();
        const uint32_t skv = sbase + AT_ST0 + st * AT_STRIDE;

        // ---- S = (Qh+Ql) @ K^T ----
        float sacc[8][4];
#pragma unroll
        for (int i = 0; i < 8; i++)
#pragma unroll
            for (int e = 0; e < 4; e++) sacc[i][e] = 0.f;

#pragma unroll
        for (int s = 0; s < 4; s++) {
            const int cx = s * 2 + (mat >> 1);
            uint32_t qh[4], ql[4];
            {
                int row = wid * 16 + (mat & 1) * 8 + rin;
                uint32_t off = swz(row, cx);
                ldsm_x4(qh, sbase + AT_SQH + off);
                ldsm_x4(ql, sbase + AT_SQL + off);
            }
#pragma unroll
            for (int t = 0; t < 4; t++) {
                int krow = t * 16 + (mat & 1) * 8 + rin;
                uint32_t off = swz(krow, cx);
                uint32_t th[4];
                ldsm_x4(th, skv + AT_K + off);
                uint32_t bh0[2] = {th[0], th[2]}, bh1[2] = {th[1], th[3]};
                mma16816h(sacc[2*t],   qh, bh0);
                mma16816h(sacc[2*t+1], qh, bh1);
                mma16816h(sacc[2*t],   ql, bh0);
                mma16816h(sacc[2*t+1], ql, bh1);
            }
        }

        // ---- online softmax (warp-local) ----
        float mx0 = -1e30f, mx1 = -1e30f;
#pragma unroll
        for (int i = 0; i < 8; i++) {
            mx0 = fmaxf(mx0, fmaxf(sacc[i][0], sacc[i][1]));
            mx1 = fmaxf(mx1, fmaxf(sacc[i][2], sacc[i][3]));
        }
        mx0 = fmaxf(mx0, __shfl_xor_sync(0xffffffffu, mx0, 1));
        mx0 = fmaxf(mx0, __shfl_xor_sync(0xffffffffu, mx0, 2));
        mx1 = fmaxf(mx1, __shfl_xor_sync(0xffffffffu, mx1, 1));
        mx1 = fmaxf(mx1, __shfl_xor_sync(0xffffffffu, mx1, 2));
        float mn0 = fmaxf(m0, mx0), mn1 = fmaxf(m1, mx1);
        float al0 = __expf(m0 - mn0), al1 = __expf(m1 - mn1);
        m0 = mn0; m1 = mn1;
        float rs0 = 0.f, rs1 = 0.f;
#pragma unroll
        for (int i = 0; i < 8; i++) {
            sacc[i][0] = __expf(sacc[i][0] - mn0);
            sacc[i][1] = __expf(sacc[i][1] - mn0);
            sacc[i][2] = __expf(sacc[i][2] - mn1);
            sacc[i][3] = __expf(sacc[i][3] - mn1);
            rs0 += sacc[i][0] + sacc[i][1];
            rs1 += sacc[i][2] + sacc[i][3];
        }
        rs0 += __shfl_xor_sync(0xffffffffu, rs0, 1);
        rs0 += __shfl_xor_sync(0xffffffffu, rs0, 2);
        rs1 += __shfl_xor_sync(0xffffffffu, rs1, 1);
        rs1 += __shfl_xor_sync(0xffffffffu, rs1, 2);
        l0 = l0 * al0 + rs0;
        l1 = l1 * al1 + rs1;
#pragma unroll
        for (int i = 0; i < 8; i++) {
            oacc[i][0] *= al0; oacc[i][1] *= al0;
            oacc[i][2] *= al1; oacc[i][3] *= al1;
        }

        // ---- O += (Ph+Pl) @ V ----
#pragma unroll
        for (int s = 0; s < 4; s++) {
            uint32_t ph[4], pl[4];
            {
                float e0 = sacc[2*s][0], e1 = sacc[2*s][1];
                float e2 = sacc[2*s][2], e3 = sacc[2*s][3];
                float f0 = sacc[2*s+1][0], f1 = sacc[2*s+1][1];
                float f2 = sacc[2*s+1][2], f3 = sacc[2*s+1][3];
                __half2 t0 = __floats2half2_rn(e0, e1);
                __half2 t1 = __floats2half2_rn(e2, e3);
                __half2 t2 = __floats2half2_rn(f0, f1);
                __half2 t3 = __floats2half2_rn(f2, f3);
                ph[0] = *(uint32_t*)&t0; ph[1] = *(uint32_t*)&t1;
                ph[2] = *(uint32_t*)&t2; ph[3] = *(uint32_t*)&t3;
                __half2 u0 = __floats2half2_rn(
                    e0 - __half2float(__low2half(t0)),
                    e1 - __half2float(__high2half(t0)));
                __half2 u1 = __floats2half2_rn(
                    e2 - __half2float(__low2half(t1)),
                    e3 - __half2float(__high2half(t1)));
                __half2 u2 = __floats2half2_rn(
                    f0 - __half2float(__low2half(t2)),
                    f1 - __half2float(__high2half(t2)));
                __half2 u3 = __floats2half2_rn(
                    f2 - __half2float(__low2half(t3)),
                    f3 - __half2float(__high2half(t3)));
                pl[0] = *(uint32_t*)&u0; pl[1] = *(uint32_t*)&u1;
                pl[2] = *(uint32_t*)&u2; pl[3] = *(uint32_t*)&u3;
            }
#pragma unroll
            for (int t = 0; t < 4; t++) {
                int vrow = s * 16 + (mat >> 1) * 8 + rin;
                int cxv = t * 2 + (mat & 1);
                uint32_t off = swz(vrow, cxv);
                uint32_t th[4];
                ldsm_x4_t(th, skv + AT_V + off);
                uint32_t vh0[2] = {th[0], th[2]}, vh1[2] = {th[1], th[3]};
                mma16816h(oacc[2*t],   ph, vh0);
                mma16816h(oacc[2*t+1], ph, vh1);
                mma16816h(oacc[2*t],   pl, vh0);
                mma16816h(oacc[2*t+1], pl, vh1);
            }
        }
        __syncthreads();
        if (kt + 2 < 16) issue_kv(st, kt + 2);
    };

#pragma unroll 1
    for (int kt = 0; kt < 16; kt += 2) {
        astep(kt, 0);
        astep(kt + 1, 1);
    }

    // epilogue: normalize, split fp16 hi/lo, write [B*N, C]
    float inv0 = 1.f / l0, inv1 = 1.f / l1;
    int r0 = q0 + wid * 16 + g;
    int r1 = r0 + 8;
#pragma unroll
    for (int nj = 0; nj < 8; nj++) {
        int col = h * 64 + nj * 8 + c4 * 2;
        {
            float v0 = oacc[nj][0] * inv0, v1 = oacc[nj][1] * inv0;
            __half2 hi2 = __floats2half2_rn(v0, v1);
            __half2 lo2 = __floats2half2_rn(
                v0 - __half2float(__low2half(hi2)),
                v1 - __half2float(__high2half(hi2)));
            size_t idx = (size_t)(b * 1024 + r0) * 1024 + col;
            *(uint32_t*)&g_oh[idx] = *(uint32_t*)&hi2;
            *(uint32_t*)&g_ol[idx] = *(uint32_t*)&lo2;
        }
        {
            float v0 = oacc[nj][2] * inv1, v1 = oacc[nj][3] * inv1;
            __half2 hi2 = __floats2half2_rn(v0, v1);
            __half2 lo2 = __floats2half2_rn(
                v0 - __half2float(__low2half(hi2)),
                v1 - __half2float(__high2half(hi2)));
            size_t idx = (size_t)(b * 1024 + r1) * 1024 + col;
            *(uint32_t*)&g_oh[idx] = *(uint32_t*)&hi2;
            *(uint32_t*)&g_ol[idx] = *(uint32_t*)&lo2;
        }
    }
}

// ---------------------------------------------------------------------------
extern "C" void kernel_launch(void* const* d_in, const int* in_sizes, int n_in,
                              void* d_out, int out_size) {
    const float* x     = (const float*)d_in[0];
    const float* w_in  = (const float*)d_in[1];
    const float* b_in  = (const float*)d_in[2];
    const float* w_out = (const float*)d_in[3];
    const float* b_out = (const float*)d_in[4];
    float* out = (float*)d_out;

    static bool attr_set = false;
    if (!attr_set) {
        cudaFuncSetAttribute(gemm_fp16_kernel,
                             cudaFuncAttributeMaxDynamicSharedMemorySize, GEMM_SMEM);
        cudaFuncSetAttribute(attn_mma_kernel,
                             cudaFuncAttributeMaxDynamicSharedMemorySize, ATTN_SMEM);
        attr_set = true;
    }

    __half *xh, *xl, *wi, *wo, *oh, *ol;
    cudaGetSymbolAddress((void**)&xh, g_xh);
    cudaGetSymbolAddress((void**)&xl, g_xl);
    cudaGetSymbolAddress((void**)&wi, g_wi);
    cudaGetSymbolAddress((void**)&wo, g_wo);
    cudaGetSymbolAddress((void**)&oh, g_oh);
    cudaGetSymbolAddress((void**)&ol, g_ol);

    const int nx = BB*NN*CC, nwi = 3*CC*CC, nwo = CC*CC;

    // 1) prep: fp16 dual-split of x; fp16 casts of weights
    split_fp16_kernel<<<(nx + 255) / 256, 256>>>(x, xh, xl, nx);
    cvt_fp16_kernel<<<(nwi + 255) / 256, 256>>>(w_in, wi, nwi);
    cvt_fp16_kernel<<<(nwo + 255) / 256, 256>>>(w_out, wo, nwo);

    // 2) QKV projection (fp16 asymmetric split; writes fp16 hi/lo q/k/v)
    gemm_fp16_kernel<<<dim3(24, 64), 256, GEMM_SMEM>>>(
        xh, xl, wi, b_in, nullptr, 0);

    // 3) fp16 flash attention (reads q hi+lo, k hi, v hi)
    attn_mma_kernel<<<dim3(8, 128), 256, ATTN_SMEM>>>();

    // 4) out projection (fp16 asymmetric split)
    gemm_fp16_kernel<<<dim3(8, 64), 256, GEMM_SMEM>>>(
        oh, ol, wo, b_out, out, 1);
}